// round 17
// baseline (speedup 1.0000x reference)
#include <cuda_runtime.h>
#include <cuda_bf16.h>
#include <stdint.h>

#define NN 8192
#define FF 512
#define EPSF 1e-5f

// -------- scratch (static __device__ — no allocations allowed) --------
__device__ float g_rowsum[NN];
__device__ float g_colsum[NN];
__device__ __nv_bfloat16 g_Y[(size_t)NN * FF];   // Y = diag(r_inv) * X, bf16, row-major

// ============================ K0: zero accumulators ============================
__global__ void k0_zero(float* out) {
    int i = blockIdx.x * blockDim.x + threadIdx.x;
    if (i < NN) g_colsum[i] = 0.0f;
    if (i == 0) out[0] = 0.0f;
}

// ============================ K1: row + col sums of adj =======================
// 148 balanced CTAs; 256 threads span the FULL row. 2-row interleave doubles
// load-level parallelism. Register col-accumulators; rowsum via shuffle.
__global__ __launch_bounds__(256) void k1_sums(const float* __restrict__ adj) {
    __shared__ float srow[64];
    int tid = threadIdx.x, lane = tid & 31;
    int r0 = (int)(((long long)blockIdx.x * NN) / 148);
    int r1 = (int)(((long long)(blockIdx.x + 1) * NN) / 148);
    for (int i = tid; i < 64; i += 256) srow[i] = 0.0f;
    __syncthreads();

    float4 ca[8];
#pragma unroll
    for (int j = 0; j < 8; ++j) ca[j] = make_float4(0.f, 0.f, 0.f, 0.f);

    int r = r0;
    for (; r + 1 < r1; r += 2) {
        const float4* __restrict__ rw0 = (const float4*)(adj + (size_t)r * NN);
        const float4* __restrict__ rw1 = (const float4*)(adj + (size_t)(r + 1) * NN);
        float rp0 = 0.0f, rp1 = 0.0f;
#pragma unroll
        for (int j = 0; j < 8; ++j) {
            float4 v0 = __ldg(rw0 + tid + 256 * j);
            float4 v1 = __ldg(rw1 + tid + 256 * j);
            ca[j].x += v0.x + v1.x; ca[j].y += v0.y + v1.y;
            ca[j].z += v0.z + v1.z; ca[j].w += v0.w + v1.w;
            rp0 += (v0.x + v0.y) + (v0.z + v0.w);
            rp1 += (v1.x + v1.y) + (v1.z + v1.w);
        }
#pragma unroll
        for (int o = 16; o; o >>= 1) {
            rp0 += __shfl_down_sync(0xffffffffu, rp0, o);
            rp1 += __shfl_down_sync(0xffffffffu, rp1, o);
        }
        if (lane == 0) {
            atomicAdd(&srow[r - r0], rp0);
            atomicAdd(&srow[r + 1 - r0], rp1);
        }
    }
    if (r < r1) {
        const float4* __restrict__ rw0 = (const float4*)(adj + (size_t)r * NN);
        float rp0 = 0.0f;
#pragma unroll
        for (int j = 0; j < 8; ++j) {
            float4 v0 = __ldg(rw0 + tid + 256 * j);
            ca[j].x += v0.x; ca[j].y += v0.y; ca[j].z += v0.z; ca[j].w += v0.w;
            rp0 += (v0.x + v0.y) + (v0.z + v0.w);
        }
#pragma unroll
        for (int o = 16; o; o >>= 1) rp0 += __shfl_down_sync(0xffffffffu, rp0, o);
        if (lane == 0) atomicAdd(&srow[r - r0], rp0);
    }
    __syncthreads();
    for (int i = tid; i < r1 - r0; i += 256) g_rowsum[r0 + i] = srow[i];
#pragma unroll
    for (int j = 0; j < 8; ++j) {
        int c = (tid + 256 * j) * 4;
        atomicAdd(&g_colsum[c + 0], ca[j].x);
        atomicAdd(&g_colsum[c + 1], ca[j].y);
        atomicAdd(&g_colsum[c + 2], ca[j].z);
        atomicAdd(&g_colsum[c + 3], ca[j].w);
    }
}

// ============================ K2: r_inv, term1, Y=bf16(r*X) ====================
__global__ __launch_bounds__(256) void k2_prep(const float* __restrict__ X, float* out) {
    __shared__ float sterm[8];
    int wid = threadIdx.x >> 5, lane = threadIdx.x & 31;
    int row = blockIdx.x * 8 + wid;
    float d = 0.5f * (g_rowsum[row] + g_colsum[row]);   // degree of A=(adj+adjT)/2
    float rinv = rsqrtf(d + EPSF);
    const float4* __restrict__ x4 = (const float4*)(X + (size_t)row * FF);
    float s2 = 0.0f;
#pragma unroll
    for (int q = 0; q < 4; ++q) {
        float4 v = __ldg(x4 + q * 32 + lane);
        s2 += v.x * v.x + v.y * v.y + v.z * v.z + v.w * v.w;
        __nv_bfloat162* yp = (__nv_bfloat162*)(g_Y + (size_t)row * FF + (size_t)(q * 32 + lane) * 4);
        yp[0] = __floats2bfloat162_rn(v.x * rinv, v.y * rinv);
        yp[1] = __floats2bfloat162_rn(v.z * rinv, v.w * rinv);
    }
#pragma unroll
    for (int o = 16; o; o >>= 1) s2 += __shfl_down_sync(0xffffffffu, s2, o);
    if (lane == 0) sterm[wid] = (d / (d + EPSF)) * s2;
    __syncthreads();
    if (threadIdx.x == 0) {
        float t = 0.0f;
#pragma unroll
        for (int w = 0; w < 8; ++w) t += sterm[w];
        atomicAdd(out, t);
    }
}

// ============================ K3: S = sum adj .* (Y Y^T), triangular ==========
// 148 CTAs x 512 threads, 16 warps (4x4 of 32x32), 128x128 tiles, bi<=bj.
// A = Y[bi] (128x512) SMEM-RESIDENT across the CTA's tile range (reloaded only
// on bi change via LDG->STS). B = Y[bj] streamed in 8 chunks of 64 K-cols via a
// 4-stage cp.async ring with wait_group 2 (prefetch distance 3): the per-chunk
// barrier no longer waits on memory. Epilogue: adj LDG (R6 form), once per tile.

#define ABSTR  1040u                     // A row stride (1024 + 16 pad)
#define BSTR   144u                      // B row stride (128 + 16 pad)
#define OFF_A  0u
#define OFF_B  133120u                   // 128*1040
#define BSTG   18432u                    // 128*144 per ring stage
#define OFF_RED (133120u + 4u * 18432u)  // 206848
#define K3_SMEM (206848u + 128u)

__device__ __forceinline__ void cpasync16(uint32_t dst, const void* src) {
    asm volatile("cp.async.cg.shared.global [%0], [%1], 16;"
                 :: "r"(dst), "l"(src) : "memory");
}
__device__ __forceinline__ void cpcommit() {
    asm volatile("cp.async.commit_group;" ::: "memory");
}
__device__ __forceinline__ void cpwait2() {
    asm volatile("cp.async.wait_group 2;" ::: "memory");
}
__device__ __forceinline__ void ldmx4(uint32_t* r, uint32_t addr) {
    asm volatile("ldmatrix.sync.aligned.m8n8.x4.shared.b16 {%0,%1,%2,%3}, [%4];"
                 : "=r"(r[0]), "=r"(r[1]), "=r"(r[2]), "=r"(r[3]) : "r"(addr));
}
__device__ __forceinline__ void mma16816(float* c, const uint32_t* a,
                                         uint32_t b0, uint32_t b1) {
    asm volatile(
        "mma.sync.aligned.m16n8k16.row.col.f32.bf16.bf16.f32 "
        "{%0,%1,%2,%3}, {%4,%5,%6,%7}, {%8,%9}, {%0,%1,%2,%3};"
        : "+f"(c[0]), "+f"(c[1]), "+f"(c[2]), "+f"(c[3])
        : "r"(a[0]), "r"(a[1]), "r"(a[2]), "r"(a[3]), "r"(b0), "r"(b1));
}

// B chunk: 128 rows x 64 K-cols of Y[bj] -> ring stage (1024 segs, 2/thread).
__device__ __forceinline__ void load_B(uint32_t sb, int stage, int bj, int c,
                                       int tid) {
    const char* bsrc = (const char*)(g_Y + (size_t)bj * 128 * FF) + c * 128;
    uint32_t bb = sb + OFF_B + (uint32_t)stage * BSTG;
#pragma unroll
    for (int u = 0; u < 2; ++u) {
        int g2 = tid + 512 * u;
        int r = g2 >> 3, s = g2 & 7;
        cpasync16(bb + (uint32_t)(r * BSTR + s * 16),
                  bsrc + (size_t)r * 1024 + s * 16);
    }
}

__global__ void __launch_bounds__(512, 1) k3_tri(const float* __restrict__ adj,
                                                 float* out) {
    extern __shared__ char smc[];
    uint32_t sb = (uint32_t)__cvta_generic_to_shared(smc);
    const int tid = threadIdx.x, lane = tid & 31, wid = tid >> 5;
    const int wm = wid >> 2, wn = wid & 3;   // 4x4 warp grid, 32x32 tiles

    int t0 = (int)(((long long)blockIdx.x * 2080) / 148);
    int t1 = (int)(((long long)(blockIdx.x + 1) * 2080) / 148);

    int bi = 0, rem = t0;
    while (rem >= 64 - bi) { rem -= 64 - bi; ++bi; }
    int bj = bi + rem;

    // preload B chunks 0..2 of the first tile into ring stages 0..2
#pragma unroll
    for (int p = 0; p < 3; ++p) { load_B(sb, p, bj, p, tid); cpcommit(); }

    const uint32_t aoffb = (uint32_t)((wm * 32 + (lane & 15)) * ABSTR + (lane >> 4) * 16);
    const uint32_t boff  = (uint32_t)((wn * 32 + (lane & 15)) * BSTR + (lane >> 4) * 16);

    float acc[2][4][4];
#pragma unroll
    for (int mt = 0; mt < 2; ++mt)
#pragma unroll
        for (int nt = 0; nt < 4; ++nt)
#pragma unroll
            for (int e = 0; e < 4; ++e) acc[mt][nt][e] = 0.0f;
    float sacc = 0.0f;

    int cur_bi = -1;
    int q = 0;
    for (int t = t0; t < t1; ++t) {
        int bin = bi, bjn = bj + 1;          // next tile (row-major triangle)
        if (bjn >= 64) { bin = bi + 1; bjn = bin; }
        const bool offd = (bi != bj);

        if (bi != cur_bi) {                  // (re)load resident A = Y[bi]
            __syncthreads();                 // nobody still reading old A
            const char* asrc = (const char*)(g_Y + (size_t)bi * 128 * FF);
            for (int i = tid; i < 8192; i += 512) {
                int r = i >> 6, s = i & 63;
                uint4 v = *(const uint4*)(asrc + (size_t)r * 1024 + s * 16);
                *(uint4*)(smc + OFF_A + (uint32_t)(r * ABSTR + s * 16)) = v;
            }
            cur_bi = bi;                     // visible after next chunk-top sync
        }

        for (int c = 0; c < 8; ++c, ++q) {
            cpwait2();                       // chunk q landed >=2 chunks ago
            __syncthreads();                 // ring-stage reuse + A visibility
            int cn = c + 3;
            int tt = t + (cn >> 3);
            if (tt < t1)                     // prefetch chunk q+3
                load_B(sb, (q + 3) & 3, (cn >= 8) ? bjn : bj, cn & 7, tid);
            cpcommit();                      // one group per chunk, always

            uint32_t ab = sb + OFF_A + aoffb + (uint32_t)(c * 128);
            uint32_t bb = sb + OFF_B + (uint32_t)(q & 3) * BSTG + boff;
#pragma unroll
            for (int ks = 0; ks < 4; ++ks) {
                uint32_t afr[2][4], bfr[2][4];
                ldmx4(afr[0], ab + ks * 32);
                ldmx4(afr[1], ab + 16 * ABSTR + ks * 32);
                ldmx4(bfr[0], bb + ks * 32);
                ldmx4(bfr[1], bb + 16 * BSTR + ks * 32);
#pragma unroll
                for (int mt = 0; mt < 2; ++mt)
#pragma unroll
                    for (int nt = 0; nt < 4; ++nt) {
                        const uint32_t* bf = bfr[nt >> 1];
                        uint32_t b0 = (nt & 1) ? bf[1] : bf[0];
                        uint32_t b1 = (nt & 1) ? bf[3] : bf[2];
                        mma16816(acc[mt][nt], afr[mt], b0, b1);
                    }
            }
        }

        // ---- epilogue: weight = adj(I,J) (+ adj(J,I)^T if off-diagonal) ----
        {
            const int rb = bi * 128 + wm * 32 + (lane >> 2);
            const int cb = bj * 128 + wn * 32 + (lane & 3) * 2;
#pragma unroll
            for (int mt = 0; mt < 2; ++mt)
#pragma unroll
                for (int h = 0; h < 2; ++h) {
                    int r = rb + mt * 16 + h * 8;
                    const float* __restrict__ rowp = adj + (size_t)r * NN + cb;
#pragma unroll
                    for (int nt = 0; nt < 4; ++nt) {
                        float2 d = __ldg((const float2*)(rowp + nt * 8));
                        float w0 = d.x, w1 = d.y;
                        if (offd) {
                            int cc = cb + nt * 8;
                            w0 += __ldg(adj + (size_t)cc * NN + r);
                            w1 += __ldg(adj + (size_t)(cc + 1) * NN + r);
                        }
                        float* a = acc[mt][nt];
                        sacc += w0 * a[h * 2 + 0] + w1 * a[h * 2 + 1];
                    }
                }
#pragma unroll
            for (int mt = 0; mt < 2; ++mt)
#pragma unroll
                for (int nt = 0; nt < 4; ++nt)
#pragma unroll
                    for (int e = 0; e < 4; ++e) acc[mt][nt][e] = 0.0f;
        }
        bi = bin; bj = bjn;
    }

    // ---- block reduce, subtract S ----
#pragma unroll
    for (int o = 16; o; o >>= 1) sacc += __shfl_down_sync(0xffffffffu, sacc, o);
    float* wacc = (float*)(smc + OFF_RED);
    __syncthreads();
    if (lane == 0) wacc[wid] = sacc;
    __syncthreads();
    if (tid == 0) {
        float s = 0.0f;
#pragma unroll
        for (int w = 0; w < 16; ++w) s += wacc[w];
        atomicAdd(out, -s);
    }
}

// ============================ launch ============================
extern "C" void kernel_launch(void* const* d_in, const int* in_sizes, int n_in,
                              void* d_out, int out_size) {
    const float* adj = (const float*)d_in[0];
    const float* X   = (const float*)d_in[1];
    float* out = (float*)d_out;

    cudaFuncSetAttribute(k3_tri, cudaFuncAttributeMaxDynamicSharedMemorySize,
                         K3_SMEM);

    k0_zero<<<32, 256>>>(out);
    k1_sums<<<148, 256>>>(adj);
    k2_prep<<<1024, 256>>>(X, out);
    k3_tri<<<148, 512, K3_SMEM>>>(adj, out);
}